// round 2
// baseline (speedup 1.0000x reference)
#include <cuda_runtime.h>

// Problem shape constants (fixed by the dataset)
#define MAX_NODES 50000
#define FD        128      // IN_FEAT == OUT_FEAT == 128
#define NRELS     4

// Scratch: hW[r][n][128]  and  hF[r][n][256] (gamma | beta)
__device__ float g_hW[NRELS * MAX_NODES * 128];   // 102.4 MB
__device__ float g_hF[NRELS * MAX_NODES * 256];   // 204.8 MB

typedef unsigned long long u64;

// Packed f32x2 helpers (Blackwell sm_100+). Fallback keeps correctness if the
// packed form is unavailable to the assembler.
#if defined(__CUDA_ARCH__) && (__CUDA_ARCH__ >= 1000)
#define FMA2(d, a, b)   asm("fma.rn.f32x2 %0, %1, %2, %0;" : "+l"(d) : "l"(a), "l"(b))
#else
#define FMA2(d, a, b) do {                                                    \
    float _dl, _dh, _al, _ah, _bl, _bh;                                       \
    asm("mov.b64 {%0, %1}, %2;" : "=f"(_dl), "=f"(_dh) : "l"(d));             \
    asm("mov.b64 {%0, %1}, %2;" : "=f"(_al), "=f"(_ah) : "l"(a));             \
    asm("mov.b64 {%0, %1}, %2;" : "=f"(_bl), "=f"(_bh) : "l"(b));             \
    _dl = fmaf(_al, _bl, _dl); _dh = fmaf(_ah, _bh, _dh);                     \
    asm("mov.b64 %0, {%1, %2};" : "=l"(d) : "f"(_dl), "f"(_dh));              \
} while (0)
#endif
#define DUP2(d, s)      asm("mov.b64 %0, {%1, %1};" : "=l"(d) : "f"(s))
#define UNPACK2(lo, hi, v) asm("mov.b64 {%0, %1}, %2;" : "=f"(lo), "=f"(hi) : "l"(v))

// ---------------------------------------------------------------------------
// Fused GEMM: C[N x 1664] = feat[N x 128] @ [W_rel(4x128x128) | film_rel(4x128x256) | loop_w(128x128)]
// Column tiles (each 128 wide):
//   ct 0..3   -> g_hW rel=ct
//   ct 4..11  -> g_hF rel=(ct-4)/2, half=(ct-4)&1  (gamma half / beta half)
//   ct 12     -> out (+ h_bias)
// Block: 256 threads, 128x128 output tile, K=128 fully resident.
// A stored transposed in SMEM: As[k][m]; B: Bs[k][n].
// Each thread: 8 rows (as 4 f32x2 pairs) x 8 cols -> 32 f32x2 accumulators.
// ---------------------------------------------------------------------------
__global__ __launch_bounds__(256, 1)
void gemm_kernel(const float* __restrict__ feat,
                 const float* __restrict__ W_rel,
                 const float* __restrict__ film_rel,
                 const float* __restrict__ loop_w,
                 const float* __restrict__ h_bias,
                 float* __restrict__ out,
                 int N)
{
    extern __shared__ float sm[];
    float* As = sm;                 // [128][128]  (k-major, transposed)
    float* Bs = sm + 128 * 128;     // [128][128]  (k-major)

    const int tid = threadIdx.x;
    const int tx  = tid & 15;       // n-direction (16)
    const int ty  = tid >> 4;       // m-direction (16)
    const int m0  = ty * 8;
    const int n0  = tx * 8;
    const int m_base = blockIdx.x * 128;

    // ---- Load A tile (transposed). Guard rows beyond N with zeros. ----
    #pragma unroll
    for (int it = 0; it < 16; ++it) {
        int li = it * 256 + tid;        // 0..4095 float4s
        int m  = li >> 5;               // 0..127
        int k4 = (li & 31) * 4;         // 0,4,..,124
        float4 v = make_float4(0.f, 0.f, 0.f, 0.f);
        int row = m_base + m;
        if (row < N)
            v = *reinterpret_cast<const float4*>(feat + (size_t)row * FD + k4);
        As[(k4 + 0) * 128 + m] = v.x;
        As[(k4 + 1) * 128 + m] = v.y;
        As[(k4 + 2) * 128 + m] = v.z;
        As[(k4 + 3) * 128 + m] = v.w;
    }
    __syncthreads();

    for (int ct = 0; ct < 13; ++ct) {
        // ---- Pick B source for this column tile ----
        const float* bptr;
        int strideD;
        if (ct < 4)       { bptr = W_rel + (size_t)ct * FD * 128; strideD = 128; }
        else if (ct < 12) {
            int idx = ct - 4, rel = idx >> 1, half = idx & 1;
            bptr = film_rel + (size_t)rel * FD * 256 + half * 128;
            strideD = 256;
        }
        else              { bptr = loop_w; strideD = 128; }

        // ---- Load B tile: Bs[k][n] ----
        #pragma unroll
        for (int it = 0; it < 16; ++it) {
            int li = it * 256 + tid;
            int d  = li >> 5;
            int j4 = (li & 31) * 4;
            float4 v = *reinterpret_cast<const float4*>(bptr + (size_t)d * strideD + j4);
            *reinterpret_cast<float4*>(&Bs[d * 128 + j4]) = v;
        }
        __syncthreads();

        // ---- Compute ----
        u64 acc[4][8];
        #pragma unroll
        for (int p = 0; p < 4; ++p)
            #pragma unroll
            for (int j = 0; j < 8; ++j) acc[p][j] = 0ull;

        #pragma unroll 8
        for (int k = 0; k < 128; ++k) {
            const float* arow = &As[k * 128 + m0];
            u64 a0 = *reinterpret_cast<const u64*>(arow + 0);
            u64 a1 = *reinterpret_cast<const u64*>(arow + 2);
            u64 a2 = *reinterpret_cast<const u64*>(arow + 4);
            u64 a3 = *reinterpret_cast<const u64*>(arow + 6);
            float4 b0 = *reinterpret_cast<const float4*>(&Bs[k * 128 + n0]);
            float4 b1 = *reinterpret_cast<const float4*>(&Bs[k * 128 + n0 + 4]);
            float bv[8] = {b0.x, b0.y, b0.z, b0.w, b1.x, b1.y, b1.z, b1.w};
            #pragma unroll
            for (int j = 0; j < 8; ++j) {
                u64 bd; DUP2(bd, bv[j]);
                FMA2(acc[0][j], a0, bd);
                FMA2(acc[1][j], a1, bd);
                FMA2(acc[2][j], a2, bd);
                FMA2(acc[3][j], a3, bd);
            }
        }
        __syncthreads();   // Bs about to be overwritten next iteration

        // ---- Epilogue: scatter the 128-wide tile to its destination ----
        float* obase;
        int so;
        if (ct < 4)       { obase = g_hW + (size_t)ct * N * 128; so = 128; }
        else if (ct < 12) {
            int idx = ct - 4, rel = idx >> 1, half = idx & 1;
            obase = g_hF + (size_t)rel * N * 256 + half * 128;
            so = 256;
        }
        else              { obase = out; so = 128; }

        float bias8[8];
        if (ct == 12) {
            #pragma unroll
            for (int j = 0; j < 8; ++j) bias8[j] = __ldg(h_bias + n0 + j);
        }

        #pragma unroll
        for (int p = 0; p < 4; ++p) {
            float lo[8], hi[8];
            #pragma unroll
            for (int j = 0; j < 8; ++j) UNPACK2(lo[j], hi[j], acc[p][j]);
            if (ct == 12) {
                #pragma unroll
                for (int j = 0; j < 8; ++j) { lo[j] += bias8[j]; hi[j] += bias8[j]; }
            }
            int r = m_base + m0 + 2 * p;
            if (r < N) {
                float* o = obase + (size_t)r * so + n0;
                *reinterpret_cast<float4*>(o)     = make_float4(lo[0], lo[1], lo[2], lo[3]);
                *reinterpret_cast<float4*>(o + 4) = make_float4(lo[4], lo[5], lo[6], lo[7]);
            }
            if (r + 1 < N) {
                float* o = obase + (size_t)(r + 1) * so + n0;
                *reinterpret_cast<float4*>(o)     = make_float4(hi[0], hi[1], hi[2], hi[3]);
                *reinterpret_cast<float4*>(o + 4) = make_float4(hi[4], hi[5], hi[6], hi[7]);
            }
        }
    }
}

// ---------------------------------------------------------------------------
// Edge kernel: one warp per edge.
//   m  = hW[et][src]   (128 f)
//   g,b = hF[et][dst]  (gamma first 128, beta last 128)
//   out[dst] += relu(g*m + b)   via red.global.add.v4.f32 (no return atomics)
// ---------------------------------------------------------------------------
__global__ __launch_bounds__(256)
void edge_kernel(const int* __restrict__ src, const int* __restrict__ dst,
                 const int* __restrict__ et, float* __restrict__ out,
                 int E, int N)
{
    int gwid = (blockIdx.x * blockDim.x + threadIdx.x) >> 5;
    if (gwid >= E) return;
    int lane = threadIdx.x & 31;

    int s = __ldg(src + gwid);
    int d = __ldg(dst + gwid);
    int r = __ldg(et  + gwid);

    const float4* mW = reinterpret_cast<const float4*>(g_hW + ((size_t)r * N + s) * 128);
    const float4* mF = reinterpret_cast<const float4*>(g_hF + ((size_t)r * N + d) * 256);

    float4 m = mW[lane];
    float4 g = mF[lane];        // gamma
    float4 b = mF[lane + 32];   // beta

    float4 v;
    v.x = fmaxf(fmaf(g.x, m.x, b.x), 0.f);
    v.y = fmaxf(fmaf(g.y, m.y, b.y), 0.f);
    v.z = fmaxf(fmaf(g.z, m.z, b.z), 0.f);
    v.w = fmaxf(fmaf(g.w, m.w, b.w), 0.f);

    float* o = out + (size_t)d * 128 + lane * 4;
    asm volatile("red.global.add.v4.f32 [%0], {%1, %2, %3, %4};"
                 :: "l"(o), "f"(v.x), "f"(v.y), "f"(v.z), "f"(v.w)
                 : "memory");
}

// ---------------------------------------------------------------------------
extern "C" void kernel_launch(void* const* d_in, const int* in_sizes, int n_in,
                              void* d_out, int out_size)
{
    const float* feat   = (const float*)d_in[0];
    const int*   src    = (const int*)  d_in[1];
    const int*   dst    = (const int*)  d_in[2];
    const int*   etypes = (const int*)  d_in[3];
    const float* W_rel  = (const float*)d_in[4];
    const float* film   = (const float*)d_in[5];
    const float* bias   = (const float*)d_in[6];
    const float* loopw  = (const float*)d_in[7];
    float* out = (float*)d_out;

    const int N = in_sizes[0] / FD;     // 50000
    const int E = in_sizes[1];          // 800000

    const int smem = 2 * 128 * 128 * (int)sizeof(float);   // 128 KB
    cudaFuncSetAttribute(gemm_kernel, cudaFuncAttributeMaxDynamicSharedMemorySize, smem);

    int mtiles = (N + 127) / 128;
    gemm_kernel<<<mtiles, 256, smem>>>(feat, W_rel, film, loopw, bias, out, N);

    int wblocks = (E + 7) / 8;          // 8 warps (edges) per 256-thread block
    edge_kernel<<<wblocks, 256>>>(src, dst, etypes, out, E, N);
}

// round 5
// speedup vs baseline: 1.7788x; 1.7788x over previous
#include <cuda_runtime.h>
#include <cuda_bf16.h>
#include <stdint.h>

#define MAX_NODES 50000
#define FD        128
#define NRELS     4
#define NTILES    13

// Scratch: hW[r][n][128]  and  hF[r][n][256] (gamma | beta)
__device__ float g_hW[NRELS * MAX_NODES * 128];   // 102.4 MB
__device__ float g_hF[NRELS * MAX_NODES * 256];   // 204.8 MB
// Pre-swizzled bf16 weight tiles: per tile 32KB hi + 32KB lo
__device__ unsigned char g_Bw[NTILES * 65536];    // 832 KB (L2-resident)

// ---------------------------------------------------------------------------
// Swizzled byte mapping for a 128x128 bf16 tile stored [row][k]:
//   row stride 256B; 16B chunks XOR-permuted by row&7 -> conflict-free ldmatrix
// ---------------------------------------------------------------------------
__host__ __device__ __forceinline__ uint32_t amap(int row, int k2 /*byte off in k*/) {
    return (uint32_t)(row * 256 + ((((k2 >> 4) ^ (row & 7)) << 4) | (k2 & 15)));
}

__device__ __forceinline__ uint32_t smem_u32(const void* p) {
    uint32_t a;
    asm("{ .reg .u64 t; cvta.to.shared.u64 t, %1; cvt.u32.u64 %0, t; }"
        : "=r"(a) : "l"(p));
    return a;
}

__device__ __forceinline__ void ldsm_x4(uint32_t* r, uint32_t addr) {
    asm volatile("ldmatrix.sync.aligned.m8n8.x4.shared.b16 {%0,%1,%2,%3}, [%4];"
                 : "=r"(r[0]), "=r"(r[1]), "=r"(r[2]), "=r"(r[3]) : "r"(addr));
}
__device__ __forceinline__ void ldsm_x2(uint32_t* r, uint32_t addr) {
    asm volatile("ldmatrix.sync.aligned.m8n8.x2.shared.b16 {%0,%1}, [%2];"
                 : "=r"(r[0]), "=r"(r[1]) : "r"(addr));
}
__device__ __forceinline__ void mma16816(float* c, const uint32_t* a, const uint32_t* b) {
    asm volatile("mma.sync.aligned.m16n8k16.row.col.f32.bf16.bf16.f32 "
                 "{%0,%1,%2,%3}, {%4,%5,%6,%7}, {%8,%9}, {%0,%1,%2,%3};"
                 : "+f"(c[0]), "+f"(c[1]), "+f"(c[2]), "+f"(c[3])
                 : "r"(a[0]), "r"(a[1]), "r"(a[2]), "r"(a[3]), "r"(b[0]), "r"(b[1]));
}
#define CP_ASYNC16(dst, src) \
    asm volatile("cp.async.ca.shared.global [%0], [%1], 16;" :: "r"(dst), "l"(src) : "memory")
#define CP_COMMIT() asm volatile("cp.async.commit_group;" ::: "memory")
#define CP_WAIT(n)  asm volatile("cp.async.wait_group %0;" :: "n"(n) : "memory")

// Split fp32 pair -> packed bf16 hi word + lo word
__device__ __forceinline__ void split2(float v0, float v1, uint32_t& hi, uint32_t& lo) {
    __nv_bfloat16 h0 = __float2bfloat16_rn(v0);
    __nv_bfloat16 h1 = __float2bfloat16_rn(v1);
    __nv_bfloat16 l0 = __float2bfloat16_rn(v0 - __bfloat162float(h0));
    __nv_bfloat16 l1 = __float2bfloat16_rn(v1 - __bfloat162float(h1));
    hi = (uint32_t)__bfloat16_as_ushort(h0) | ((uint32_t)__bfloat16_as_ushort(h1) << 16);
    lo = (uint32_t)__bfloat16_as_ushort(l0) | ((uint32_t)__bfloat16_as_ushort(l1) << 16);
}

// ---------------------------------------------------------------------------
// Prep: convert weights -> bf16 hi/lo, transposed to [n][k], pre-swizzled.
// One block per column tile (13 total).
// ---------------------------------------------------------------------------
__global__ __launch_bounds__(256)
void prep_weights(const float* __restrict__ W_rel,
                  const float* __restrict__ film_rel,
                  const float* __restrict__ loop_w)
{
    const int ct  = blockIdx.x;
    const int tid = threadIdx.x;

    const float* bptr;
    int strideD;
    if (ct < 4)       { bptr = W_rel + (size_t)ct * FD * 128; strideD = 128; }
    else if (ct < 12) {
        int idx = ct - 4, rel = idx >> 1, half = idx & 1;
        bptr = film_rel + (size_t)rel * FD * 256 + half * 128;
        strideD = 256;
    }
    else              { bptr = loop_w; strideD = 128; }

    unsigned char* dhi = g_Bw + (size_t)ct * 65536;
    unsigned char* dlo = dhi + 32768;

    #pragma unroll
    for (int it = 0; it < 16; ++it) {
        int li = it * 256 + tid;
        int n  = li & 127;
        int d4 = (li >> 7) * 4;         // k element base (0,4,...,124)
        uint32_t hiw[2], low[2];
        #pragma unroll
        for (int h = 0; h < 2; ++h) {
            float v0 = __ldg(bptr + (size_t)(d4 + 2*h)     * strideD + n);
            float v1 = __ldg(bptr + (size_t)(d4 + 2*h + 1) * strideD + n);
            split2(v0, v1, hiw[h], low[h]);
        }
        uint32_t b = amap(n, d4 * 2);
        *reinterpret_cast<uint2*>(dhi + b) = make_uint2(hiw[0], hiw[1]);
        *reinterpret_cast<uint2*>(dlo + b) = make_uint2(low[0], low[1]);
    }
}

// ---------------------------------------------------------------------------
// GEMM via mma.sync bf16 3-pass split: D = Ahi*Bhi + Ahi*Blo + Alo*Bhi.
// SMEM: A hi (32K) | A lo (32K) | B double buffer (2 x 64K) = 192K
// ---------------------------------------------------------------------------
#define SO_A_HI 0
#define SO_A_LO 32768
#define SO_B    65536
#define SMEM_TOT (65536 + 2 * 65536)

__global__ __launch_bounds__(256, 1)
void gemm_mma_kernel(const float* __restrict__ feat,
                     const float* __restrict__ h_bias,
                     float* __restrict__ out,
                     int Nn)
{
    extern __shared__ unsigned char smem[];
    const uint32_t sb = smem_u32(smem);
    const int tid  = threadIdx.x;
    const int wid  = tid >> 5;
    const int lane = tid & 31;
    const int m_base = blockIdx.x * 128;

    // ---- Convert A tile (feat rows) into hi/lo SMEM, swizzled ----
    #pragma unroll
    for (int it = 0; it < 16; ++it) {
        int li = it * 256 + tid;
        int m  = li >> 5;               // 0..127
        int k4 = (li & 31) * 4;         // 0..124
        float4 v = make_float4(0.f, 0.f, 0.f, 0.f);
        int row = m_base + m;
        if (row < Nn)
            v = *reinterpret_cast<const float4*>(feat + (size_t)row * FD + k4);
        uint32_t hiw[2], low[2];
        split2(v.x, v.y, hiw[0], low[0]);
        split2(v.z, v.w, hiw[1], low[1]);
        uint32_t b = amap(m, k4 * 2);
        *reinterpret_cast<uint2*>(smem + SO_A_HI + b) = make_uint2(hiw[0], hiw[1]);
        *reinterpret_cast<uint2*>(smem + SO_A_LO + b) = make_uint2(low[0], low[1]);
    }

    // ---- Warp tiling: 2 (m) x 4 (n) warps; warp tile 64x32 ----
    const int wm = (wid & 1) * 64;
    const int wn = (wid >> 1) * 32;
    const int lrow_a = lane & 15;           // ldmatrix.x4 row within 16
    const int lkh_a  = lane >> 4;           // k-half select
    const int lrow_b = lane & 7;            // ldmatrix.x2 row within 8
    const int lkh_b  = (lane >> 3) & 1;
    const int xr7    = lane & 7;            // row&7 (invariant across mt/nt)

    uint32_t rowoffA[4], rowoffB[4];
    #pragma unroll
    for (int mt = 0; mt < 4; ++mt) rowoffA[mt] = (uint32_t)((wm + mt * 16 + lrow_a) * 256);
    #pragma unroll
    for (int nt = 0; nt < 4; ++nt) rowoffB[nt] = (uint32_t)((wn + nt * 8 + lrow_b) * 256);

    const uint32_t sA_hi = sb + SO_A_HI;
    const uint32_t sA_lo = sb + SO_A_LO;

    // ---- Prefetch B tile 0 ----
    {
        const unsigned char* src = g_Bw;
        uint32_t dst = sb + SO_B;
        #pragma unroll
        for (int i = 0; i < 16; ++i) {
            int idx = i * 256 + tid;
            CP_ASYNC16(dst + idx * 16, src + (size_t)idx * 16);
        }
        CP_COMMIT();
    }

    for (int ct = 0; ct < NTILES; ++ct) {
        if (ct + 1 < NTILES) {
            const unsigned char* src = g_Bw + (size_t)(ct + 1) * 65536;
            uint32_t dst = sb + SO_B + ((ct + 1) & 1) * 65536;
            #pragma unroll
            for (int i = 0; i < 16; ++i) {
                int idx = i * 256 + tid;
                CP_ASYNC16(dst + idx * 16, src + (size_t)idx * 16);
            }
            CP_COMMIT();
            CP_WAIT(1);
        } else {
            CP_WAIT(0);
        }
        __syncthreads();

        const uint32_t sB_hi = sb + SO_B + (ct & 1) * 65536;
        const uint32_t sB_lo = sB_hi + 32768;

        float acc[4][4][4];
        #pragma unroll
        for (int mt = 0; mt < 4; ++mt)
            #pragma unroll
            for (int nt = 0; nt < 4; ++nt)
                #pragma unroll
                for (int q = 0; q < 4; ++q) acc[mt][nt][q] = 0.f;

        // ---- Phase 1: A-hi x (B-hi, B-lo) ----
        #pragma unroll
        for (int ks = 0; ks < 8; ++ks) {
            uint32_t cA = (uint32_t)((((2 * ks + lkh_a) ^ xr7) & 15) << 4);
            uint32_t cB = (uint32_t)((((2 * ks + lkh_b) ^ xr7) & 15) << 4);
            uint32_t a[4][4];
            #pragma unroll
            for (int mt = 0; mt < 4; ++mt) ldsm_x4(a[mt], sA_hi + rowoffA[mt] + cA);
            uint32_t bh[4][2], bl[4][2];
            #pragma unroll
            for (int nt = 0; nt < 4; ++nt) ldsm_x2(bh[nt], sB_hi + rowoffB[nt] + cB);
            #pragma unroll
            for (int nt = 0; nt < 4; ++nt) ldsm_x2(bl[nt], sB_lo + rowoffB[nt] + cB);
            #pragma unroll
            for (int mt = 0; mt < 4; ++mt)
                #pragma unroll
                for (int nt = 0; nt < 4; ++nt) {
                    mma16816(acc[mt][nt], a[mt], bh[nt]);
                    mma16816(acc[mt][nt], a[mt], bl[nt]);
                }
        }
        // ---- Phase 2: A-lo x B-hi ----
        #pragma unroll
        for (int ks = 0; ks < 8; ++ks) {
            uint32_t cA = (uint32_t)((((2 * ks + lkh_a) ^ xr7) & 15) << 4);
            uint32_t cB = (uint32_t)((((2 * ks + lkh_b) ^ xr7) & 15) << 4);
            uint32_t a[4][4];
            #pragma unroll
            for (int mt = 0; mt < 4; ++mt) ldsm_x4(a[mt], sA_lo + rowoffA[mt] + cA);
            uint32_t bh[4][2];
            #pragma unroll
            for (int nt = 0; nt < 4; ++nt) ldsm_x2(bh[nt], sB_hi + rowoffB[nt] + cB);
            #pragma unroll
            for (int mt = 0; mt < 4; ++mt)
                #pragma unroll
                for (int nt = 0; nt < 4; ++nt)
                    mma16816(acc[mt][nt], a[mt], bh[nt]);
        }

        // ---- Epilogue ----
        float* obase;
        int so;
        if (ct < 4)       { obase = g_hW + (size_t)ct * Nn * 128; so = 128; }
        else if (ct < 12) {
            int idx = ct - 4, rel = idx >> 1, half = idx & 1;
            obase = g_hF + (size_t)rel * Nn * 256 + half * 128;
            so = 256;
        }
        else              { obase = out; so = 128; }

        float2 bias2[4];
        if (ct == 12) {
            #pragma unroll
            for (int nt = 0; nt < 4; ++nt)
                bias2[nt] = *reinterpret_cast<const float2*>(
                    h_bias + wn + nt * 8 + (lane & 3) * 2);
        }

        #pragma unroll
        for (int mt = 0; mt < 4; ++mt) {
            int r0 = m_base + wm + mt * 16 + (lane >> 2);
            #pragma unroll
            for (int nt = 0; nt < 4; ++nt) {
                int col = wn + nt * 8 + (lane & 3) * 2;
                float2 v0 = make_float2(acc[mt][nt][0], acc[mt][nt][1]);
                float2 v1 = make_float2(acc[mt][nt][2], acc[mt][nt][3]);
                if (ct == 12) {
                    v0.x += bias2[nt].x; v0.y += bias2[nt].y;
                    v1.x += bias2[nt].x; v1.y += bias2[nt].y;
                }
                if (r0 < Nn)
                    *reinterpret_cast<float2*>(obase + (size_t)r0 * so + col) = v0;
                if (r0 + 8 < Nn)
                    *reinterpret_cast<float2*>(obase + (size_t)(r0 + 8) * so + col) = v1;
            }
        }
        __syncthreads();   // all ldmatrix reads done before buffer reuse
    }
}

// ---------------------------------------------------------------------------
// Edge kernel: one warp per edge (near HBM roofline @ ~194us).
// ---------------------------------------------------------------------------
__global__ __launch_bounds__(256)
void edge_kernel(const int* __restrict__ src, const int* __restrict__ dst,
                 const int* __restrict__ et, float* __restrict__ out,
                 int E, int N)
{
    int gwid = (blockIdx.x * blockDim.x + threadIdx.x) >> 5;
    if (gwid >= E) return;
    int lane = threadIdx.x & 31;

    int s = __ldg(src + gwid);
    int d = __ldg(dst + gwid);
    int r = __ldg(et  + gwid);

    const float4* mW = reinterpret_cast<const float4*>(g_hW + ((size_t)r * N + s) * 128);
    const float4* mF = reinterpret_cast<const float4*>(g_hF + ((size_t)r * N + d) * 256);

    float4 m = mW[lane];
    float4 g = mF[lane];        // gamma
    float4 b = mF[lane + 32];   // beta

    float4 v;
    v.x = fmaxf(fmaf(g.x, m.x, b.x), 0.f);
    v.y = fmaxf(fmaf(g.y, m.y, b.y), 0.f);
    v.z = fmaxf(fmaf(g.z, m.z, b.z), 0.f);
    v.w = fmaxf(fmaf(g.w, m.w, b.w), 0.f);

    float* o = out + (size_t)d * 128 + lane * 4;
    asm volatile("red.global.add.v4.f32 [%0], {%1, %2, %3, %4};"
                 :: "l"(o), "f"(v.x), "f"(v.y), "f"(v.z), "f"(v.w)
                 : "memory");
}

// ---------------------------------------------------------------------------
extern "C" void kernel_launch(void* const* d_in, const int* in_sizes, int n_in,
                              void* d_out, int out_size)
{
    const float* feat   = (const float*)d_in[0];
    const int*   src    = (const int*)  d_in[1];
    const int*   dst    = (const int*)  d_in[2];
    const int*   etypes = (const int*)  d_in[3];
    const float* W_rel  = (const float*)d_in[4];
    const float* film   = (const float*)d_in[5];
    const float* bias   = (const float*)d_in[6];
    const float* loopw  = (const float*)d_in[7];
    float* out = (float*)d_out;

    const int N = in_sizes[0] / FD;     // 50000
    const int E = in_sizes[1];          // 800000

    cudaFuncSetAttribute(gemm_mma_kernel,
                         cudaFuncAttributeMaxDynamicSharedMemorySize, SMEM_TOT);

    prep_weights<<<NTILES, 256>>>(W_rel, film, loopw);

    int mtiles = (N + 127) / 128;       // 391
    gemm_mma_kernel<<<mtiles, 256, SMEM_TOT>>>(feat, bias, out, N);

    int wblocks = (E + 7) / 8;
    edge_kernel<<<wblocks, 256>>>(src, dst, etypes, out, E, N);
}

// round 6
// speedup vs baseline: 2.1190x; 1.1912x over previous
#include <cuda_runtime.h>
#include <cuda_fp16.h>
#include <stdint.h>

#define MAX_NODES 50000
#define FD        128
#define NRELS     4
#define NTILES    13

// Scratch: hW[r][n][128]  and  hF[r][n][256] (gamma | beta)
__device__ float g_hW[NRELS * MAX_NODES * 128];   // 102.4 MB
__device__ float g_hF[NRELS * MAX_NODES * 256];   // 204.8 MB
// Pre-swizzled fp16 weight tiles (hi only): 32KB per tile
__device__ unsigned char g_Bw[NTILES * 32768];    // 416 KB (L2-resident)

// ---------------------------------------------------------------------------
// Swizzled byte mapping for a 128x128 fp16 tile stored [row][k]:
//   row stride 256B; 16B chunks XOR-permuted by row&7 -> conflict-free ldmatrix
// ---------------------------------------------------------------------------
__host__ __device__ __forceinline__ uint32_t amap(int row, int k2 /*byte off in k*/) {
    return (uint32_t)(row * 256 + ((((k2 >> 4) ^ (row & 7)) << 4) | (k2 & 15)));
}

__device__ __forceinline__ uint32_t smem_u32(const void* p) {
    uint32_t a;
    asm("{ .reg .u64 t; cvta.to.shared.u64 t, %1; cvt.u32.u64 %0, t; }"
        : "=r"(a) : "l"(p));
    return a;
}

__device__ __forceinline__ void ldsm_x4(uint32_t* r, uint32_t addr) {
    asm volatile("ldmatrix.sync.aligned.m8n8.x4.shared.b16 {%0,%1,%2,%3}, [%4];"
                 : "=r"(r[0]), "=r"(r[1]), "=r"(r[2]), "=r"(r[3]) : "r"(addr));
}
__device__ __forceinline__ void ldsm_x2(uint32_t* r, uint32_t addr) {
    asm volatile("ldmatrix.sync.aligned.m8n8.x2.shared.b16 {%0,%1}, [%2];"
                 : "=r"(r[0]), "=r"(r[1]) : "r"(addr));
}
__device__ __forceinline__ void mma16816(float* c, const uint32_t* a, const uint32_t* b) {
    asm volatile("mma.sync.aligned.m16n8k16.row.col.f32.f16.f16.f32 "
                 "{%0,%1,%2,%3}, {%4,%5,%6,%7}, {%8,%9}, {%0,%1,%2,%3};"
                 : "+f"(c[0]), "+f"(c[1]), "+f"(c[2]), "+f"(c[3])
                 : "r"(a[0]), "r"(a[1]), "r"(a[2]), "r"(a[3]), "r"(b[0]), "r"(b[1]));
}
#define CP_ASYNC16(dst, src) \
    asm volatile("cp.async.ca.shared.global [%0], [%1], 16;" :: "r"(dst), "l"(src) : "memory")
#define CP_COMMIT() asm volatile("cp.async.commit_group;" ::: "memory")
#define CP_WAIT(n)  asm volatile("cp.async.wait_group %0;" :: "n"(n) : "memory")

// fp16 split: hi = rn(x), lo = rn(x - hi)  (packed pairs)
__device__ __forceinline__ void splitA2(float v0, float v1, uint32_t& hi, uint32_t& lo) {
    __half h0 = __float2half_rn(v0);
    __half h1 = __float2half_rn(v1);
    __half l0 = __float2half_rn(v0 - __half2float(h0));
    __half l1 = __float2half_rn(v1 - __half2float(h1));
    hi = (uint32_t)__half_as_ushort(h0) | ((uint32_t)__half_as_ushort(h1) << 16);
    lo = (uint32_t)__half_as_ushort(l0) | ((uint32_t)__half_as_ushort(l1) << 16);
}
__device__ __forceinline__ uint32_t cvtB2(float v0, float v1) {
    __half h0 = __float2half_rn(v0);
    __half h1 = __float2half_rn(v1);
    return (uint32_t)__half_as_ushort(h0) | ((uint32_t)__half_as_ushort(h1) << 16);
}

// ---------------------------------------------------------------------------
// Prep: weights -> fp16 (hi only), transposed to [n][k], pre-swizzled.
// 8 blocks per column tile (104 total) to avoid launch-latency domination.
// ---------------------------------------------------------------------------
__global__ __launch_bounds__(256)
void prep_weights(const float* __restrict__ W_rel,
                  const float* __restrict__ film_rel,
                  const float* __restrict__ loop_w)
{
    const int ct   = blockIdx.x >> 3;
    const int part = blockIdx.x & 7;
    const int tid  = threadIdx.x;

    const float* bptr;
    int strideD;
    if (ct < 4)       { bptr = W_rel + (size_t)ct * FD * 128; strideD = 128; }
    else if (ct < 12) {
        int idx = ct - 4, rel = idx >> 1, half = idx & 1;
        bptr = film_rel + (size_t)rel * FD * 256 + half * 128;
        strideD = 256;
    }
    else              { bptr = loop_w; strideD = 128; }

    unsigned char* dhi = g_Bw + (size_t)ct * 32768;

    #pragma unroll
    for (int s = 0; s < 2; ++s) {
        int li = (part * 2 + s) * 256 + tid;   // 0..4095
        int n  = li & 127;
        int d4 = (li >> 7) * 4;                // k element base
        uint32_t w0 = cvtB2(__ldg(bptr + (size_t)(d4    ) * strideD + n),
                            __ldg(bptr + (size_t)(d4 + 1) * strideD + n));
        uint32_t w1 = cvtB2(__ldg(bptr + (size_t)(d4 + 2) * strideD + n),
                            __ldg(bptr + (size_t)(d4 + 3) * strideD + n));
        *reinterpret_cast<uint2*>(dhi + amap(n, d4 * 2)) = make_uint2(w0, w1);
    }
}

// ---------------------------------------------------------------------------
// GEMM via mma.sync fp16 2-pass split: D = Ahi*Bhi + Alo*Bhi  (= a * Bhi)
// SMEM: A hi (32K) | A lo (32K) | B double buffer (2 x 32K) = 128K
// ---------------------------------------------------------------------------
#define SO_A_HI 0
#define SO_A_LO 32768
#define SO_B    65536
#define SMEM_TOT (65536 + 2 * 32768)

__global__ __launch_bounds__(256, 1)
void gemm_mma_kernel(const float* __restrict__ feat,
                     const float* __restrict__ h_bias,
                     float* __restrict__ out,
                     int Nn)
{
    extern __shared__ unsigned char smem[];
    const uint32_t sb = smem_u32(smem);
    const int tid  = threadIdx.x;
    const int wid  = tid >> 5;
    const int lane = tid & 31;
    const int m_base = blockIdx.x * 128;

    // ---- Convert A tile (feat rows) into fp16 hi/lo SMEM, swizzled ----
    #pragma unroll
    for (int it = 0; it < 16; ++it) {
        int li = it * 256 + tid;
        int m  = li >> 5;               // 0..127
        int k4 = (li & 31) * 4;         // 0..124
        float4 v = make_float4(0.f, 0.f, 0.f, 0.f);
        int row = m_base + m;
        if (row < Nn)
            v = *reinterpret_cast<const float4*>(feat + (size_t)row * FD + k4);
        uint32_t hiw[2], low[2];
        splitA2(v.x, v.y, hiw[0], low[0]);
        splitA2(v.z, v.w, hiw[1], low[1]);
        uint32_t b = amap(m, k4 * 2);
        *reinterpret_cast<uint2*>(smem + SO_A_HI + b) = make_uint2(hiw[0], hiw[1]);
        *reinterpret_cast<uint2*>(smem + SO_A_LO + b) = make_uint2(low[0], low[1]);
    }

    // ---- Warp tiling: 2 (m) x 4 (n) warps; warp tile 64x32 ----
    const int wm = (wid & 1) * 64;
    const int wn = (wid >> 1) * 32;
    const int lrow_a = lane & 15;
    const int lkh_a  = lane >> 4;
    const int lrow_b = lane & 7;
    const int lkh_b  = (lane >> 3) & 1;
    const int xr7    = lane & 7;

    uint32_t rowoffA[4], rowoffB[4];
    #pragma unroll
    for (int mt = 0; mt < 4; ++mt) rowoffA[mt] = (uint32_t)((wm + mt * 16 + lrow_a) * 256);
    #pragma unroll
    for (int nt = 0; nt < 4; ++nt) rowoffB[nt] = (uint32_t)((wn + nt * 8 + lrow_b) * 256);

    const uint32_t sA_hi = sb + SO_A_HI;
    const uint32_t sA_lo = sb + SO_A_LO;

    // ---- Prefetch B tile 0 (32KB: 2048 x 16B) ----
    {
        const unsigned char* src = g_Bw;
        uint32_t dst = sb + SO_B;
        #pragma unroll
        for (int i = 0; i < 8; ++i) {
            int idx = i * 256 + tid;
            CP_ASYNC16(dst + idx * 16, src + (size_t)idx * 16);
        }
        CP_COMMIT();
    }

    for (int ct = 0; ct < NTILES; ++ct) {
        if (ct + 1 < NTILES) {
            const unsigned char* src = g_Bw + (size_t)(ct + 1) * 32768;
            uint32_t dst = sb + SO_B + ((ct + 1) & 1) * 32768;
            #pragma unroll
            for (int i = 0; i < 8; ++i) {
                int idx = i * 256 + tid;
                CP_ASYNC16(dst + idx * 16, src + (size_t)idx * 16);
            }
            CP_COMMIT();
            CP_WAIT(1);
        } else {
            CP_WAIT(0);
        }
        __syncthreads();

        const uint32_t sB_hi = sb + SO_B + (ct & 1) * 32768;

        float acc[4][4][4];
        #pragma unroll
        for (int mt = 0; mt < 4; ++mt)
            #pragma unroll
            for (int nt = 0; nt < 4; ++nt)
                #pragma unroll
                for (int q = 0; q < 4; ++q) acc[mt][nt][q] = 0.f;

        // ---- 2 passes: A-hi x B-hi, then A-lo x B-hi ----
        #pragma unroll
        for (int pass = 0; pass < 2; ++pass) {
            const uint32_t sA = (pass == 0) ? sA_hi : sA_lo;
            #pragma unroll
            for (int ks = 0; ks < 8; ++ks) {
                uint32_t cA = (uint32_t)((((2 * ks + lkh_a) ^ xr7) & 15) << 4);
                uint32_t cB = (uint32_t)((((2 * ks + lkh_b) ^ xr7) & 15) << 4);
                uint32_t a[4][4];
                #pragma unroll
                for (int mt = 0; mt < 4; ++mt) ldsm_x4(a[mt], sA + rowoffA[mt] + cA);
                uint32_t bh[4][2];
                #pragma unroll
                for (int nt = 0; nt < 4; ++nt) ldsm_x2(bh[nt], sB_hi + rowoffB[nt] + cB);
                #pragma unroll
                for (int mt = 0; mt < 4; ++mt)
                    #pragma unroll
                    for (int nt = 0; nt < 4; ++nt)
                        mma16816(acc[mt][nt], a[mt], bh[nt]);
            }
        }

        // ---- Epilogue ----
        float* obase;
        int so;
        if (ct < 4)       { obase = g_hW + (size_t)ct * Nn * 128; so = 128; }
        else if (ct < 12) {
            int idx = ct - 4, rel = idx >> 1, half = idx & 1;
            obase = g_hF + (size_t)rel * Nn * 256 + half * 128;
            so = 256;
        }
        else              { obase = out; so = 128; }

        float2 bias2[4];
        if (ct == 12) {
            #pragma unroll
            for (int nt = 0; nt < 4; ++nt)
                bias2[nt] = *reinterpret_cast<const float2*>(
                    h_bias + wn + nt * 8 + (lane & 3) * 2);
        }

        #pragma unroll
        for (int mt = 0; mt < 4; ++mt) {
            int r0 = m_base + wm + mt * 16 + (lane >> 2);
            #pragma unroll
            for (int nt = 0; nt < 4; ++nt) {
                int col = wn + nt * 8 + (lane & 3) * 2;
                float2 v0 = make_float2(acc[mt][nt][0], acc[mt][nt][1]);
                float2 v1 = make_float2(acc[mt][nt][2], acc[mt][nt][3]);
                if (ct == 12) {
                    v0.x += bias2[nt].x; v0.y += bias2[nt].y;
                    v1.x += bias2[nt].x; v1.y += bias2[nt].y;
                }
                if (r0 < Nn)
                    *reinterpret_cast<float2*>(obase + (size_t)r0 * so + col) = v0;
                if (r0 + 8 < Nn)
                    *reinterpret_cast<float2*>(obase + (size_t)(r0 + 8) * so + col) = v1;
            }
        }
        __syncthreads();   // all ldmatrix reads done before buffer reuse
    }
}

// ---------------------------------------------------------------------------
// Edge kernel: one warp per edge (measured 78% of HBM spec; keep).
// ---------------------------------------------------------------------------
__global__ __launch_bounds__(256)
void edge_kernel(const int* __restrict__ src, const int* __restrict__ dst,
                 const int* __restrict__ et, float* __restrict__ out,
                 int E, int N)
{
    int gwid = (blockIdx.x * blockDim.x + threadIdx.x) >> 5;
    if (gwid >= E) return;
    int lane = threadIdx.x & 31;

    int s = __ldg(src + gwid);
    int d = __ldg(dst + gwid);
    int r = __ldg(et  + gwid);

    const float4* mW = reinterpret_cast<const float4*>(g_hW + ((size_t)r * N + s) * 128);
    const float4* mF = reinterpret_cast<const float4*>(g_hF + ((size_t)r * N + d) * 256);

    float4 m = mW[lane];
    float4 g = mF[lane];        // gamma
    float4 b = mF[lane + 32];   // beta

    float4 v;
    v.x = fmaxf(fmaf(g.x, m.x, b.x), 0.f);
    v.y = fmaxf(fmaf(g.y, m.y, b.y), 0.f);
    v.z = fmaxf(fmaf(g.z, m.z, b.z), 0.f);
    v.w = fmaxf(fmaf(g.w, m.w, b.w), 0.f);

    float* o = out + (size_t)d * 128 + lane * 4;
    asm volatile("red.global.add.v4.f32 [%0], {%1, %2, %3, %4};"
                 :: "l"(o), "f"(v.x), "f"(v.y), "f"(v.z), "f"(v.w)
                 : "memory");
}

// ---------------------------------------------------------------------------
extern "C" void kernel_launch(void* const* d_in, const int* in_sizes, int n_in,
                              void* d_out, int out_size)
{
    const float* feat   = (const float*)d_in[0];
    const int*   src    = (const int*)  d_in[1];
    const int*   dst    = (const int*)  d_in[2];
    const int*   etypes = (const int*)  d_in[3];
    const float* W_rel  = (const float*)d_in[4];
    const float* film   = (const float*)d_in[5];
    const float* bias   = (const float*)d_in[6];
    const float* loopw  = (const float*)d_in[7];
    float* out = (float*)d_out;

    const int N = in_sizes[0] / FD;     // 50000
    const int E = in_sizes[1];          // 800000

    cudaFuncSetAttribute(gemm_mma_kernel,
                         cudaFuncAttributeMaxDynamicSharedMemorySize, SMEM_TOT);

    prep_weights<<<NTILES * 8, 256>>>(W_rel, film, loopw);

    int mtiles = (N + 127) / 128;       // 391
    gemm_mma_kernel<<<mtiles, 256, SMEM_TOT>>>(feat, bias, out, N);

    int wblocks = (E + 7) / 8;
    edge_kernel<<<wblocks, 256>>>(src, dst, etypes, out, E, N);
}

// round 7
// speedup vs baseline: 2.9818x; 1.4072x over previous
#include <cuda_runtime.h>
#include <cuda_fp16.h>
#include <stdint.h>

#define MAX_NODES 50000
#define FD        128
#define NRELS     4
#define NTILES    13

// Scratch (fp16): hW[r][n][128], hF[r][n][256] (gamma | beta)
__device__ __half g_hW[NRELS * MAX_NODES * 128];   // 51.2 MB
__device__ __half g_hF[NRELS * MAX_NODES * 256];   // 102.4 MB
// Pre-swizzled fp16 weight tiles: 32KB per tile
__device__ unsigned char g_Bw[NTILES * 32768];     // 416 KB (L2-resident)

// ---------------------------------------------------------------------------
// Swizzled byte mapping for a 128x128 fp16 tile stored [row][k]:
//   row stride 256B; 16B chunks XOR-permuted by row&7 -> conflict-free ldmatrix
// ---------------------------------------------------------------------------
__host__ __device__ __forceinline__ uint32_t amap(int row, int k2 /*byte off in k*/) {
    return (uint32_t)(row * 256 + ((((k2 >> 4) ^ (row & 7)) << 4) | (k2 & 15)));
}

__device__ __forceinline__ uint32_t smem_u32(const void* p) {
    uint32_t a;
    asm("{ .reg .u64 t; cvta.to.shared.u64 t, %1; cvt.u32.u64 %0, t; }"
        : "=r"(a) : "l"(p));
    return a;
}

__device__ __forceinline__ void ldsm_x4(uint32_t* r, uint32_t addr) {
    asm volatile("ldmatrix.sync.aligned.m8n8.x4.shared.b16 {%0,%1,%2,%3}, [%4];"
                 : "=r"(r[0]), "=r"(r[1]), "=r"(r[2]), "=r"(r[3]) : "r"(addr));
}
__device__ __forceinline__ void ldsm_x2(uint32_t* r, uint32_t addr) {
    asm volatile("ldmatrix.sync.aligned.m8n8.x2.shared.b16 {%0,%1}, [%2];"
                 : "=r"(r[0]), "=r"(r[1]) : "r"(addr));
}
__device__ __forceinline__ void mma16816(float* c, const uint32_t* a, const uint32_t* b) {
    asm volatile("mma.sync.aligned.m16n8k16.row.col.f32.f16.f16.f32 "
                 "{%0,%1,%2,%3}, {%4,%5,%6,%7}, {%8,%9}, {%0,%1,%2,%3};"
                 : "+f"(c[0]), "+f"(c[1]), "+f"(c[2]), "+f"(c[3])
                 : "r"(a[0]), "r"(a[1]), "r"(a[2]), "r"(a[3]), "r"(b[0]), "r"(b[1]));
}
#define CP_ASYNC16(dst, src) \
    asm volatile("cp.async.ca.shared.global [%0], [%1], 16;" :: "r"(dst), "l"(src) : "memory")
#define CP_COMMIT() asm volatile("cp.async.commit_group;" ::: "memory")
#define CP_WAIT(n)  asm volatile("cp.async.wait_group %0;" :: "n"(n) : "memory")

__device__ __forceinline__ uint32_t cvt2h(float v0, float v1) {
    __half h0 = __float2half_rn(v0);
    __half h1 = __float2half_rn(v1);
    return (uint32_t)__half_as_ushort(h0) | ((uint32_t)__half_as_ushort(h1) << 16);
}

// ---------------------------------------------------------------------------
// Prep: weights -> fp16, transposed to [n][k], pre-swizzled. 104 blocks.
// ---------------------------------------------------------------------------
__global__ __launch_bounds__(256)
void prep_weights(const float* __restrict__ W_rel,
                  const float* __restrict__ film_rel,
                  const float* __restrict__ loop_w)
{
    const int ct   = blockIdx.x >> 3;
    const int part = blockIdx.x & 7;
    const int tid  = threadIdx.x;

    const float* bptr;
    int strideD;
    if (ct < 4)       { bptr = W_rel + (size_t)ct * FD * 128; strideD = 128; }
    else if (ct < 12) {
        int idx = ct - 4, rel = idx >> 1, half = idx & 1;
        bptr = film_rel + (size_t)rel * FD * 256 + half * 128;
        strideD = 256;
    }
    else              { bptr = loop_w; strideD = 128; }

    unsigned char* dhi = g_Bw + (size_t)ct * 32768;

    #pragma unroll
    for (int s = 0; s < 2; ++s) {
        int li = (part * 2 + s) * 256 + tid;   // 0..4095
        int n  = li & 127;
        int d4 = (li >> 7) * 4;
        uint32_t w0 = cvt2h(__ldg(bptr + (size_t)(d4    ) * strideD + n),
                            __ldg(bptr + (size_t)(d4 + 1) * strideD + n));
        uint32_t w1 = cvt2h(__ldg(bptr + (size_t)(d4 + 2) * strideD + n),
                            __ldg(bptr + (size_t)(d4 + 3) * strideD + n));
        *reinterpret_cast<uint2*>(dhi + amap(n, d4 * 2)) = make_uint2(w0, w1);
    }
}

// ---------------------------------------------------------------------------
// GEMM via mma.sync fp16 single-pass: D = Ahi * Bhi
// SMEM: A (32K) | B double buffer (2 x 32K) = 96K  -> 2 CTAs/SM
// ---------------------------------------------------------------------------
#define SO_A  0
#define SO_B  32768
#define SMEM_TOT (32768 + 2 * 32768)

__global__ __launch_bounds__(256, 2)
void gemm_mma_kernel(const float* __restrict__ feat,
                     const float* __restrict__ h_bias,
                     float* __restrict__ out,
                     int Nn)
{
    extern __shared__ unsigned char smem[];
    const uint32_t sb = smem_u32(smem);
    const int tid  = threadIdx.x;
    const int wid  = tid >> 5;
    const int lane = tid & 31;
    const int m_base = blockIdx.x * 128;

    // ---- Convert A tile (feat rows) into fp16 SMEM, swizzled ----
    #pragma unroll
    for (int it = 0; it < 16; ++it) {
        int li = it * 256 + tid;
        int m  = li >> 5;               // 0..127
        int k4 = (li & 31) * 4;         // 0..124
        float4 v = make_float4(0.f, 0.f, 0.f, 0.f);
        int row = m_base + m;
        if (row < Nn)
            v = *reinterpret_cast<const float4*>(feat + (size_t)row * FD + k4);
        uint32_t w0 = cvt2h(v.x, v.y);
        uint32_t w1 = cvt2h(v.z, v.w);
        *reinterpret_cast<uint2*>(smem + SO_A + amap(m, k4 * 2)) = make_uint2(w0, w1);
    }

    // ---- Warp tiling: 2 (m) x 4 (n) warps; warp tile 64x32 ----
    const int wm = (wid & 1) * 64;
    const int wn = (wid >> 1) * 32;
    const int lrow_a = lane & 15;
    const int lkh_a  = lane >> 4;
    const int lrow_b = lane & 7;
    const int lkh_b  = (lane >> 3) & 1;
    const int xr7    = lane & 7;

    uint32_t rowoffA[4], rowoffB[4];
    #pragma unroll
    for (int mt = 0; mt < 4; ++mt) rowoffA[mt] = (uint32_t)((wm + mt * 16 + lrow_a) * 256);
    #pragma unroll
    for (int nt = 0; nt < 4; ++nt) rowoffB[nt] = (uint32_t)((wn + nt * 8 + lrow_b) * 256);

    const uint32_t sA = sb + SO_A;

    // ---- Prefetch B tile 0 (32KB: 2048 x 16B) ----
    {
        const unsigned char* src = g_Bw;
        uint32_t dst = sb + SO_B;
        #pragma unroll
        for (int i = 0; i < 8; ++i) {
            int idx = i * 256 + tid;
            CP_ASYNC16(dst + idx * 16, src + (size_t)idx * 16);
        }
        CP_COMMIT();
    }

    for (int ct = 0; ct < NTILES; ++ct) {
        if (ct + 1 < NTILES) {
            const unsigned char* src = g_Bw + (size_t)(ct + 1) * 32768;
            uint32_t dst = sb + SO_B + ((ct + 1) & 1) * 32768;
            #pragma unroll
            for (int i = 0; i < 8; ++i) {
                int idx = i * 256 + tid;
                CP_ASYNC16(dst + idx * 16, src + (size_t)idx * 16);
            }
            CP_COMMIT();
            CP_WAIT(1);
        } else {
            CP_WAIT(0);
        }
        __syncthreads();

        const uint32_t sB = sb + SO_B + (ct & 1) * 32768;

        float acc[4][4][4];
        #pragma unroll
        for (int mt = 0; mt < 4; ++mt)
            #pragma unroll
            for (int nt = 0; nt < 4; ++nt)
                #pragma unroll
                for (int q = 0; q < 4; ++q) acc[mt][nt][q] = 0.f;

        // ---- Single pass: A x B ----
        #pragma unroll
        for (int ks = 0; ks < 8; ++ks) {
            uint32_t cA = (uint32_t)((((2 * ks + lkh_a) ^ xr7) & 15) << 4);
            uint32_t cB = (uint32_t)((((2 * ks + lkh_b) ^ xr7) & 15) << 4);
            uint32_t a[4][4];
            #pragma unroll
            for (int mt = 0; mt < 4; ++mt) ldsm_x4(a[mt], sA + rowoffA[mt] + cA);
            uint32_t bh[4][2];
            #pragma unroll
            for (int nt = 0; nt < 4; ++nt) ldsm_x2(bh[nt], sB + rowoffB[nt] + cB);
            #pragma unroll
            for (int mt = 0; mt < 4; ++mt)
                #pragma unroll
                for (int nt = 0; nt < 4; ++nt)
                    mma16816(acc[mt][nt], a[mt], bh[nt]);
        }

        // ---- Epilogue ----
        if (ct == 12) {
            // out (fp32) + bias
            float2 bias2[4];
            #pragma unroll
            for (int nt = 0; nt < 4; ++nt)
                bias2[nt] = *reinterpret_cast<const float2*>(
                    h_bias + wn + nt * 8 + (lane & 3) * 2);
            #pragma unroll
            for (int mt = 0; mt < 4; ++mt) {
                int r0 = m_base + wm + mt * 16 + (lane >> 2);
                #pragma unroll
                for (int nt = 0; nt < 4; ++nt) {
                    int col = wn + nt * 8 + (lane & 3) * 2;
                    float2 v0 = make_float2(acc[mt][nt][0] + bias2[nt].x,
                                            acc[mt][nt][1] + bias2[nt].y);
                    float2 v1 = make_float2(acc[mt][nt][2] + bias2[nt].x,
                                            acc[mt][nt][3] + bias2[nt].y);
                    if (r0 < Nn)
                        *reinterpret_cast<float2*>(out + (size_t)r0 * 128 + col) = v0;
                    if (r0 + 8 < Nn)
                        *reinterpret_cast<float2*>(out + (size_t)(r0 + 8) * 128 + col) = v1;
                }
            }
        } else {
            // scratch (fp16)
            __half* obase;
            int so;
            if (ct < 4) { obase = g_hW + (size_t)ct * Nn * 128; so = 128; }
            else {
                int idx = ct - 4, rel = idx >> 1, half = idx & 1;
                obase = g_hF + (size_t)rel * Nn * 256 + half * 128;
                so = 256;
            }
            #pragma unroll
            for (int mt = 0; mt < 4; ++mt) {
                int r0 = m_base + wm + mt * 16 + (lane >> 2);
                #pragma unroll
                for (int nt = 0; nt < 4; ++nt) {
                    int col = wn + nt * 8 + (lane & 3) * 2;
                    uint32_t h0 = cvt2h(acc[mt][nt][0], acc[mt][nt][1]);
                    uint32_t h1 = cvt2h(acc[mt][nt][2], acc[mt][nt][3]);
                    if (r0 < Nn)
                        *reinterpret_cast<uint32_t*>(obase + (size_t)r0 * so + col) = h0;
                    if (r0 + 8 < Nn)
                        *reinterpret_cast<uint32_t*>(obase + (size_t)(r0 + 8) * so + col) = h1;
                }
            }
        }
        __syncthreads();   // all ldmatrix reads done before buffer reuse
    }
}

// ---------------------------------------------------------------------------
// Edge kernel: one warp per edge. fp16 gathers, fp32 math + fp32 atomics.
//   m  = hW[et][src] (128 h), g|b = hF[et][dst] (256 h)
//   out[dst] += relu(g*m + b) via red.global.add.v4.f32
// ---------------------------------------------------------------------------
__global__ __launch_bounds__(256)
void edge_kernel(const int* __restrict__ src, const int* __restrict__ dst,
                 const int* __restrict__ et, float* __restrict__ out,
                 int E, int N)
{
    int gwid = (blockIdx.x * blockDim.x + threadIdx.x) >> 5;
    if (gwid >= E) return;
    int lane = threadIdx.x & 31;

    int s = __ldg(src + gwid);
    int d = __ldg(dst + gwid);
    int r = __ldg(et  + gwid);

    const uint2* mW = reinterpret_cast<const uint2*>(g_hW + ((size_t)r * N + s) * 128);
    const uint2* mF = reinterpret_cast<const uint2*>(g_hF + ((size_t)r * N + d) * 256);

    uint2 mu = mW[lane];            // 4 halves of m
    uint2 gu = mF[lane];            // 4 halves of gamma
    uint2 bu = mF[lane + 32];       // 4 halves of beta

    float2 m0 = __half22float2(*reinterpret_cast<const __half2*>(&mu.x));
    float2 m1 = __half22float2(*reinterpret_cast<const __half2*>(&mu.y));
    float2 g0 = __half22float2(*reinterpret_cast<const __half2*>(&gu.x));
    float2 g1 = __half22float2(*reinterpret_cast<const __half2*>(&gu.y));
    float2 b0 = __half22float2(*reinterpret_cast<const __half2*>(&bu.x));
    float2 b1 = __half22float2(*reinterpret_cast<const __half2*>(&bu.y));

    float4 v;
    v.x = fmaxf(fmaf(g0.x, m0.x, b0.x), 0.f);
    v.y = fmaxf(fmaf(g0.y, m0.y, b0.y), 0.f);
    v.z = fmaxf(fmaf(g1.x, m1.x, b1.x), 0.f);
    v.w = fmaxf(fmaf(g1.y, m1.y, b1.y), 0.f);

    float* o = out + (size_t)d * 128 + lane * 4;
    asm volatile("red.global.add.v4.f32 [%0], {%1, %2, %3, %4};"
                 :: "l"(o), "f"(v.x), "f"(v.y), "f"(v.z), "f"(v.w)
                 : "memory");
}

// ---------------------------------------------------------------------------
extern "C" void kernel_launch(void* const* d_in, const int* in_sizes, int n_in,
                              void* d_out, int out_size)
{
    const float* feat   = (const float*)d_in[0];
    const int*   src    = (const int*)  d_in[1];
    const int*   dst    = (const int*)  d_in[2];
    const int*   etypes = (const int*)  d_in[3];
    const float* W_rel  = (const float*)d_in[4];
    const float* film   = (const float*)d_in[5];
    const float* bias   = (const float*)d_in[6];
    const float* loopw  = (const float*)d_in[7];
    float* out = (float*)d_out;

    const int N = in_sizes[0] / FD;     // 50000
    const int E = in_sizes[1];          // 800000

    cudaFuncSetAttribute(gemm_mma_kernel,
                         cudaFuncAttributeMaxDynamicSharedMemorySize, SMEM_TOT);

    prep_weights<<<NTILES * 8, 256>>>(W_rel, film, loopw);

    int mtiles = (N + 127) / 128;       // 391
    gemm_mma_kernel<<<mtiles, 256, SMEM_TOT>>>(feat, bias, out, N);

    int wblocks = (E + 7) / 8;
    edge_kernel<<<wblocks, 256>>>(src, dst, etypes, out, E, N);
}